// round 1
// baseline (speedup 1.0000x reference)
#include <cuda_runtime.h>

#define BATCH 8
#define T 1024
#define D 768
#define F 12288
#define CDIM 48
#define KSEL 3072
#define NPART 16
#define TCHUNK (T / NPART)

// -------- device scratch (allocation-free rule: static __device__ globals) ----
__device__ float g_part[BATCH * NPART * D];           // partial pooled sums
__device__ float g_ck[BATCH * F];                     // control logits
__device__ int   g_sel[BATCH * KSEL];                 // selected feature indices
__device__ float g_h[(size_t)BATCH * T * KSEL];       // relu(x @ Wmfc_sel^T), ~100 MB
__device__ float g_wpT[(size_t)F * D];                // w_proj transposed [F][D]

// ============================================================================
// K1: partial sequence-mean pool. grid = BATCH*NPART, block = 256.
// Deterministic two-stage reduction (no float atomics).
// ============================================================================
__global__ void pool_partial_kernel(const float* __restrict__ x) {
    const int b = blockIdx.x >> 4;
    const int s = blockIdx.x & 15;
    const float* xp = x + ((size_t)b * T + (size_t)s * TCHUNK) * D;
    for (int d = threadIdx.x; d < D; d += blockDim.x) {
        float acc = 0.f;
        #pragma unroll 4
        for (int t = 0; t < TCHUNK; t++) acc += xp[(size_t)t * D + d];
        g_part[(size_t)blockIdx.x * D + d] = acc;
    }
}

// ============================================================================
// K2: ck = relu(pooled @ w1^T) @ w2^T.  grid = BATCH, block = 1024.
// ============================================================================
__global__ void __launch_bounds__(1024) ck_kernel(const float* __restrict__ w1,
                                                  const float* __restrict__ w2) {
    const int b = blockIdx.x;
    __shared__ float pooled_s[D];
    __shared__ float tmp_s[CDIM];
    const int tid = threadIdx.x;

    // finish pooled mean
    for (int d = tid; d < D; d += blockDim.x) {
        float s = 0.f;
        #pragma unroll
        for (int p = 0; p < NPART; p++) s += g_part[(size_t)(b * NPART + p) * D + d];
        pooled_s[d] = s * (1.0f / (float)T);
    }
    __syncthreads();

    // tmp = relu(pooled @ w1^T): one warp per output channel
    const int wid = tid >> 5, lane = tid & 31;
    for (int c = wid; c < CDIM; c += 32) {
        float s = 0.f;
        for (int d = lane; d < D; d += 32) s += pooled_s[d] * w1[(size_t)c * D + d];
        #pragma unroll
        for (int o = 16; o > 0; o >>= 1) s += __shfl_xor_sync(0xFFFFFFFFu, s, o);
        if (lane == 0) tmp_s[c] = fmaxf(s, 0.f);
    }
    __syncthreads();

    // ck = tmp @ w2^T  (softmax omitted: monotonic, preserves top-k set)
    for (int f = tid; f < F; f += blockDim.x) {
        const float* w2r = w2 + (size_t)f * CDIM;
        float s = 0.f;
        #pragma unroll
        for (int c = 0; c < CDIM; c++) s += tmp_s[c] * w2r[c];
        g_ck[b * F + f] = s;
    }
}

// ============================================================================
// K3: exact top-KSEL selection per batch via 4-pass MSB radix select on
// order-preserving uint keys, then DETERMINISTIC ordered compaction
// (ballot + block scan; no atomic-order dependence).
// grid = BATCH, block = 1024. 12288/1024 = 12 keys per thread.
// ============================================================================
__global__ void __launch_bounds__(1024) topk_kernel() {
    const int b = blockIdx.x;
    const float* ck = g_ck + b * F;

    __shared__ unsigned hist[256];
    __shared__ unsigned s_prefix, s_remaining;
    __shared__ int s_wcnt_gt[32], s_wcnt_eq[32];
    __shared__ int s_woff_gt[32], s_woff_eq[32];
    __shared__ int s_base_gt, s_base_eq;

    const int tid = threadIdx.x;
    unsigned keys[12];
    #pragma unroll
    for (int i = 0; i < 12; i++) {
        unsigned u = __float_as_uint(ck[i * 1024 + tid]);
        keys[i] = (u & 0x80000000u) ? ~u : (u | 0x80000000u);  // larger key = larger float
    }
    if (tid == 0) { s_prefix = 0u; s_remaining = KSEL; }
    unsigned prefix_mask = 0u;
    __syncthreads();

    // radix select: find the KSEL-th largest key (threshold)
    for (int pass = 0; pass < 4; pass++) {
        const int shift = 24 - 8 * pass;
        if (tid < 256) hist[tid] = 0u;
        __syncthreads();
        const unsigned prefix = s_prefix;
        #pragma unroll
        for (int i = 0; i < 12; i++) {
            if ((keys[i] & prefix_mask) == prefix)
                atomicAdd(&hist[(keys[i] >> shift) & 255u], 1u);
        }
        __syncthreads();
        if (tid == 0) {
            const unsigned rem = s_remaining;
            unsigned cum = 0u;  // count of keys strictly above current bin
            int bin = 255;
            for (; bin > 0; bin--) {
                if (cum + hist[bin] >= rem) break;
                cum += hist[bin];
            }
            s_remaining = rem - cum;
            s_prefix = prefix | ((unsigned)bin << shift);
        }
        prefix_mask |= (0xFFu << shift);
        __syncthreads();
    }

    const unsigned thr = s_prefix;
    const int remaining = (int)s_remaining;      // # of ==thr elements to take
    const int gt_total  = KSEL - remaining;      // # of >thr elements (all taken)

    if (tid == 0) { s_base_gt = 0; s_base_eq = 0; }
    __syncthreads();

    const int wid = tid >> 5, lane = tid & 31;
    const unsigned lmask = (1u << lane) - 1u;
    for (int i = 0; i < 12; i++) {
        const int idx = i * 1024 + tid;          // chunk covers contiguous indices
        const unsigned k = keys[i];
        const bool isgt = (k > thr);
        const bool iseq = (k == thr);
        const unsigned bg = __ballot_sync(0xFFFFFFFFu, isgt);
        const unsigned be = __ballot_sync(0xFFFFFFFFu, iseq);
        if (lane == 0) { s_wcnt_gt[wid] = __popc(bg); s_wcnt_eq[wid] = __popc(be); }
        __syncthreads();
        if (tid == 0) {
            int sg = s_base_gt, se = s_base_eq;
            for (int w = 0; w < 32; w++) {
                s_woff_gt[w] = sg; sg += s_wcnt_gt[w];
                s_woff_eq[w] = se; se += s_wcnt_eq[w];
            }
            s_base_gt = sg; s_base_eq = se;
        }
        __syncthreads();
        if (isgt) {
            const int pos = s_woff_gt[wid] + __popc(bg & lmask);
            g_sel[b * KSEL + pos] = idx;
        } else if (iseq) {
            const int er = s_woff_eq[wid] + __popc(be & lmask);
            if (er < remaining) g_sel[b * KSEL + gt_total + er] = idx;
        }
    }
}

// ============================================================================
// K4: transpose w_proj [D][F] -> g_wpT [F][D] so GEMM2 gathers contiguous rows.
// grid = (F/32, D/32), block = (32, 8).
// ============================================================================
__global__ void transpose_kernel(const float* __restrict__ wp) {
    __shared__ float tile[32][33];
    const int f0 = blockIdx.x * 32, e0 = blockIdx.y * 32;
    const int tx = threadIdx.x, ty = threadIdx.y;
    #pragma unroll
    for (int r = ty; r < 32; r += 8)
        tile[r][tx] = wp[(size_t)(e0 + r) * F + f0 + tx];
    __syncthreads();
    #pragma unroll
    for (int r = ty; r < 32; r += 8)
        g_wpT[(size_t)(f0 + r) * D + e0 + tx] = tile[tx][r];
}

// ============================================================================
// K5: GEMM1 (gathered-N): Hs[b,t,j] = relu( sum_d x[b,t,d] * Wmfc[sel[b,j],d] )
// M=1024, N=3072(sel), K=768. BM=BN=128, BK=16, 256 thr, 8x8/thread.
// grid = (KSEL/128, T/128, BATCH) = 1536 blocks.
// ============================================================================
__global__ void __launch_bounds__(256) gemm1_kernel(const float* __restrict__ x,
                                                    const float* __restrict__ wm) {
    const int b = blockIdx.z;
    const int n0 = blockIdx.x * 128;
    const int m0 = blockIdx.y * 128;
    const float* A = x + (size_t)b * T * D;
    const int* sel = g_sel + b * KSEL;
    float* Cp = g_h + (size_t)b * T * KSEL;

    __shared__ float As[16][132];   // padded: conflict-free transposed stores
    __shared__ float Bs[16][132];
    __shared__ int selc[128];

    const int tid = threadIdx.x;
    if (tid < 128) selc[tid] = sel[n0 + tid];
    __syncthreads();

    const int tx = tid & 15, ty = tid >> 4;
    float acc[8][8];
    #pragma unroll
    for (int i = 0; i < 8; i++)
        #pragma unroll
        for (int j = 0; j < 8; j++) acc[i][j] = 0.f;

    for (int k0 = 0; k0 < D; k0 += 16) {
        #pragma unroll
        for (int i = 0; i < 2; i++) {
            const int idx4 = tid + i * 256;
            const int r = idx4 >> 2;
            const int c4 = (idx4 & 3) << 2;
            const float4 va = *(const float4*)(A + (size_t)(m0 + r) * D + k0 + c4);
            As[c4 + 0][r] = va.x; As[c4 + 1][r] = va.y;
            As[c4 + 2][r] = va.z; As[c4 + 3][r] = va.w;
            const float4 vb = *(const float4*)(wm + (size_t)selc[r] * D + k0 + c4);
            Bs[c4 + 0][r] = vb.x; Bs[c4 + 1][r] = vb.y;
            Bs[c4 + 2][r] = vb.z; Bs[c4 + 3][r] = vb.w;
        }
        __syncthreads();
        #pragma unroll
        for (int k = 0; k < 16; k++) {
            float a[8], bb[8];
            *(float4*)&a[0]  = *(const float4*)&As[k][ty * 8];
            *(float4*)&a[4]  = *(const float4*)&As[k][ty * 8 + 4];
            *(float4*)&bb[0] = *(const float4*)&Bs[k][tx * 8];
            *(float4*)&bb[4] = *(const float4*)&Bs[k][tx * 8 + 4];
            #pragma unroll
            for (int i = 0; i < 8; i++)
                #pragma unroll
                for (int j = 0; j < 8; j++) acc[i][j] += a[i] * bb[j];
        }
        __syncthreads();
    }

    // fused relu epilogue
    #pragma unroll
    for (int i = 0; i < 8; i++) {
        const int row = m0 + ty * 8 + i;
        float* crow = Cp + (size_t)row * KSEL + n0 + tx * 8;
        #pragma unroll
        for (int j = 0; j < 8; j += 4) {
            float4 v;
            v.x = fmaxf(acc[i][j + 0], 0.f);
            v.y = fmaxf(acc[i][j + 1], 0.f);
            v.z = fmaxf(acc[i][j + 2], 0.f);
            v.w = fmaxf(acc[i][j + 3], 0.f);
            *(float4*)(crow + j) = v;
        }
    }
}

// ============================================================================
// K6: GEMM2 (gathered-K): out[b,t,e] = sum_j Hs[b,t,j] * wpT[sel[b,j], e]
// M=1024, N=768, K=3072. BM=64, BN=128, BK=16, 128 thr, 8x8/thread.
// grid = (D/128, T/64, BATCH) = 768 blocks -> ~1 wave at ~5 blocks/SM.
// ============================================================================
__global__ void __launch_bounds__(128) gemm2_kernel(float* __restrict__ out) {
    const int b = blockIdx.z;
    const int e0 = blockIdx.x * 128;
    const int m0 = blockIdx.y * 64;
    const float* A = g_h + (size_t)b * T * KSEL;
    const int* sel = g_sel + b * KSEL;

    __shared__ float As[16][68];
    __shared__ float Bs[16][132];

    const int tid = threadIdx.x;
    const int tx = tid & 15, ty = tid >> 4;   // ty 0..7
    float acc[8][8];
    #pragma unroll
    for (int i = 0; i < 8; i++)
        #pragma unroll
        for (int j = 0; j < 8; j++) acc[i][j] = 0.f;

    for (int k0 = 0; k0 < KSEL; k0 += 16) {
        // A tile: 64 t-rows x 16 j-cols, transposed store
        #pragma unroll
        for (int i = 0; i < 2; i++) {
            const int idx4 = tid + i * 128;
            const int r = idx4 >> 2;
            const int c4 = (idx4 & 3) << 2;
            const float4 va = *(const float4*)(A + (size_t)(m0 + r) * KSEL + k0 + c4);
            As[c4 + 0][r] = va.x; As[c4 + 1][r] = va.y;
            As[c4 + 2][r] = va.z; As[c4 + 3][r] = va.w;
        }
        // B tile: 16 gathered wpT rows x 128 e-cols, direct (k-major) store
        #pragma unroll
        for (int i = 0; i < 4; i++) {
            const int idx4 = tid + i * 128;
            const int jr = idx4 >> 5;
            const int c4 = (idx4 & 31) << 2;
            const int srow = sel[k0 + jr];     // warp-uniform -> broadcast load
            const float4 vb = *(const float4*)(g_wpT + (size_t)srow * D + e0 + c4);
            *(float4*)&Bs[jr][c4] = vb;
        }
        __syncthreads();
        #pragma unroll
        for (int k = 0; k < 16; k++) {
            float a[8], bb[8];
            *(float4*)&a[0]  = *(const float4*)&As[k][ty * 8];
            *(float4*)&a[4]  = *(const float4*)&As[k][ty * 8 + 4];
            *(float4*)&bb[0] = *(const float4*)&Bs[k][tx * 8];
            *(float4*)&bb[4] = *(const float4*)&Bs[k][tx * 8 + 4];
            #pragma unroll
            for (int i = 0; i < 8; i++)
                #pragma unroll
                for (int j = 0; j < 8; j++) acc[i][j] += a[i] * bb[j];
        }
        __syncthreads();
    }

    #pragma unroll
    for (int i = 0; i < 8; i++) {
        const int row = m0 + ty * 8 + i;
        float* orow = out + ((size_t)b * T + row) * D + e0 + tx * 8;
        #pragma unroll
        for (int j = 0; j < 8; j += 4) {
            float4 v;
            v.x = acc[i][j + 0]; v.y = acc[i][j + 1];
            v.z = acc[i][j + 2]; v.w = acc[i][j + 3];
            *(float4*)(orow + j) = v;
        }
    }
}

// ============================================================================
extern "C" void kernel_launch(void* const* d_in, const int* in_sizes, int n_in,
                              void* d_out, int out_size) {
    const float* x      = (const float*)d_in[0];
    const float* w1     = (const float*)d_in[1];
    const float* w2     = (const float*)d_in[2];
    const float* w_mfc  = (const float*)d_in[3];
    const float* w_proj = (const float*)d_in[4];
    float* out = (float*)d_out;

    pool_partial_kernel<<<BATCH * NPART, 256>>>(x);
    ck_kernel<<<BATCH, 1024>>>(w1, w2);
    topk_kernel<<<BATCH, 1024>>>();
    transpose_kernel<<<dim3(F / 32, D / 32), dim3(32, 8)>>>(w_proj);
    gemm1_kernel<<<dim3(KSEL / 128, T / 128, BATCH), 256>>>(x, w_mfc);
    gemm2_kernel<<<dim3(D / 128, T / 64, BATCH), 128>>>(out);
}

// round 8
// speedup vs baseline: 2.2340x; 2.2340x over previous
#include <cuda_runtime.h>
#include <cuda_bf16.h>
#include <cstdint>

#define BATCH 8
#define T 1024
#define D 768
#define F 12288
#define CDIM 48
#define KSEL 3072
#define NPART 16
#define TCHUNK (T / NPART)

// -------- device scratch (allocation-free rule: static __device__ globals) ----
// RULE (hard-learned R3-R7): these are referenced ONLY from device code.
// Passing them as host-side kernel args yields the host shadow address -> crash.
__device__ float g_part[BATCH * NPART * D];
__device__ float g_ck[BATCH * F];
__device__ int   g_sel[BATCH * KSEL];
__device__ __align__(16) __nv_bfloat16 g_x_hi[(size_t)BATCH * T * D];
__device__ __align__(16) __nv_bfloat16 g_x_lo[(size_t)BATCH * T * D];
__device__ __align__(16) __nv_bfloat16 g_wm_hi[(size_t)F * D];
__device__ __align__(16) __nv_bfloat16 g_wm_lo[(size_t)F * D];
__device__ __align__(16) __nv_bfloat16 g_h_hi[(size_t)BATCH * T * KSEL];
__device__ __align__(16) __nv_bfloat16 g_h_lo[(size_t)BATCH * T * KSEL];
__device__ __align__(16) __nv_bfloat16 g_bc_hi[(size_t)BATCH * D * KSEL];
__device__ __align__(16) __nv_bfloat16 g_bc_lo[(size_t)BATCH * D * KSEL];

// ============================================================================
// PTX helpers (base-target only: cp.async / ldmatrix / mma.sync)
// ============================================================================
__device__ __forceinline__ uint32_t smem_to_u32(const void* p) {
    uint32_t a;
    asm("{ .reg .u64 t; cvta.to.shared.u64 t, %1; cvt.u32.u64 %0, t; }" : "=r"(a) : "l"(p));
    return a;
}
__device__ __forceinline__ void cp_async16(uint32_t saddr, const void* gptr) {
    asm volatile("cp.async.cg.shared.global [%0], [%1], 16;" :: "r"(saddr), "l"(gptr) : "memory");
}
__device__ __forceinline__ void cp_commit() { asm volatile("cp.async.commit_group;" ::: "memory"); }
__device__ __forceinline__ void cp_wait0()  { asm volatile("cp.async.wait_group 0;" ::: "memory"); }

__device__ __forceinline__ void ldm_x4(uint32_t* r, uint32_t addr) {
    asm volatile("ldmatrix.sync.aligned.m8n8.x4.shared.b16 {%0,%1,%2,%3}, [%4];"
                 : "=r"(r[0]), "=r"(r[1]), "=r"(r[2]), "=r"(r[3]) : "r"(addr));
}
__device__ __forceinline__ void mma_bf16(float* c, const uint32_t* a, const uint32_t* b) {
    asm volatile("mma.sync.aligned.m16n8k16.row.col.f32.bf16.bf16.f32 "
                 "{%0,%1,%2,%3}, {%4,%5,%6,%7}, {%8,%9}, {%0,%1,%2,%3};"
                 : "+f"(c[0]), "+f"(c[1]), "+f"(c[2]), "+f"(c[3])
                 : "r"(a[0]), "r"(a[1]), "r"(a[2]), "r"(a[3]), "r"(b[0]), "r"(b[1]));
}
__device__ __forceinline__ uint32_t bf162_as_u32(__nv_bfloat162 v) {
    return *reinterpret_cast<uint32_t*>(&v);
}

// ============================================================================
// K1: partial sequence-mean pool (verified Round 1)
// ============================================================================
__global__ void pool_partial_kernel(const float* __restrict__ x) {
    const int b = blockIdx.x >> 4;
    const int s = blockIdx.x & 15;
    const float* xp = x + ((size_t)b * T + (size_t)s * TCHUNK) * D;
    for (int d = threadIdx.x; d < D; d += blockDim.x) {
        float acc = 0.f;
        #pragma unroll 4
        for (int t = 0; t < TCHUNK; t++) acc += xp[(size_t)t * D + d];
        g_part[(size_t)blockIdx.x * D + d] = acc;
    }
}

// ============================================================================
// K2: ck = relu(pooled @ w1^T) @ w2^T (verified Round 1)
// ============================================================================
__global__ void __launch_bounds__(1024) ck_kernel(const float* __restrict__ w1,
                                                  const float* __restrict__ w2) {
    const int b = blockIdx.x;
    __shared__ float pooled_s[D];
    __shared__ float tmp_s[CDIM];
    const int tid = threadIdx.x;

    for (int d = tid; d < D; d += blockDim.x) {
        float s = 0.f;
        #pragma unroll
        for (int p = 0; p < NPART; p++) s += g_part[(size_t)(b * NPART + p) * D + d];
        pooled_s[d] = s * (1.0f / (float)T);
    }
    __syncthreads();

    const int wid = tid >> 5, lane = tid & 31;
    for (int c = wid; c < CDIM; c += 32) {
        float s = 0.f;
        for (int d = lane; d < D; d += 32) s += pooled_s[d] * w1[(size_t)c * D + d];
        #pragma unroll
        for (int o = 16; o > 0; o >>= 1) s += __shfl_xor_sync(0xFFFFFFFFu, s, o);
        if (lane == 0) tmp_s[c] = fmaxf(s, 0.f);
    }
    __syncthreads();

    for (int f = tid; f < F; f += blockDim.x) {
        const float* w2r = w2 + (size_t)f * CDIM;
        float s = 0.f;
        #pragma unroll
        for (int c = 0; c < CDIM; c++) s += tmp_s[c] * w2r[c];
        g_ck[b * F + f] = s;
    }
}

// ============================================================================
// K3: exact top-KSEL radix select + deterministic compaction (verified Round 1)
// ============================================================================
__global__ void __launch_bounds__(1024) topk_kernel() {
    const int b = blockIdx.x;
    const float* ck = g_ck + b * F;

    __shared__ unsigned hist[256];
    __shared__ unsigned s_prefix, s_remaining;
    __shared__ int s_wcnt_gt[32], s_wcnt_eq[32];
    __shared__ int s_woff_gt[32], s_woff_eq[32];
    __shared__ int s_base_gt, s_base_eq;

    const int tid = threadIdx.x;
    unsigned keys[12];
    #pragma unroll
    for (int i = 0; i < 12; i++) {
        unsigned u = __float_as_uint(ck[i * 1024 + tid]);
        keys[i] = (u & 0x80000000u) ? ~u : (u | 0x80000000u);
    }
    if (tid == 0) { s_prefix = 0u; s_remaining = KSEL; }
    unsigned prefix_mask = 0u;
    __syncthreads();

    for (int pass = 0; pass < 4; pass++) {
        const int shift = 24 - 8 * pass;
        if (tid < 256) hist[tid] = 0u;
        __syncthreads();
        const unsigned prefix = s_prefix;
        #pragma unroll
        for (int i = 0; i < 12; i++) {
            if ((keys[i] & prefix_mask) == prefix)
                atomicAdd(&hist[(keys[i] >> shift) & 255u], 1u);
        }
        __syncthreads();
        if (tid == 0) {
            const unsigned rem = s_remaining;
            unsigned cum = 0u;
            int bin = 255;
            for (; bin > 0; bin--) {
                if (cum + hist[bin] >= rem) break;
                cum += hist[bin];
            }
            s_remaining = rem - cum;
            s_prefix = prefix | ((unsigned)bin << shift);
        }
        prefix_mask |= (0xFFu << shift);
        __syncthreads();
    }

    const unsigned thr = s_prefix;
    const int remaining = (int)s_remaining;
    const int gt_total  = KSEL - remaining;

    if (tid == 0) { s_base_gt = 0; s_base_eq = 0; }
    __syncthreads();

    const int wid = tid >> 5, lane = tid & 31;
    const unsigned lmask = (1u << lane) - 1u;
    for (int i = 0; i < 12; i++) {
        const int idx = i * 1024 + tid;
        const unsigned k = keys[i];
        const bool isgt = (k > thr);
        const bool iseq = (k == thr);
        const unsigned bg = __ballot_sync(0xFFFFFFFFu, isgt);
        const unsigned be = __ballot_sync(0xFFFFFFFFu, iseq);
        if (lane == 0) { s_wcnt_gt[wid] = __popc(bg); s_wcnt_eq[wid] = __popc(be); }
        __syncthreads();
        if (tid == 0) {
            int sg = s_base_gt, se = s_base_eq;
            for (int w = 0; w < 32; w++) {
                s_woff_gt[w] = sg; sg += s_wcnt_gt[w];
                s_woff_eq[w] = se; se += s_wcnt_eq[w];
            }
            s_base_gt = sg; s_base_eq = se;
        }
        __syncthreads();
        if (isgt) {
            const int pos = s_woff_gt[wid] + __popc(bg & lmask);
            g_sel[b * KSEL + pos] = idx;
        } else if (iseq) {
            const int er = s_woff_eq[wid] + __popc(be & lmask);
            if (er < remaining) g_sel[b * KSEL + gt_total + er] = idx;
        }
    }
}

// ============================================================================
// K4: fp32 -> bf16 hi/lo splits (x and w_mfc)
// ============================================================================
__global__ void split_x_kernel(const float* __restrict__ src) {
    const int i = blockIdx.x * blockDim.x + threadIdx.x;
    const int n4 = BATCH * T * D / 4;
    if (i >= n4) return;
    const float4 v = ((const float4*)src)[i];
    const __nv_bfloat162 h0 = __floats2bfloat162_rn(v.x, v.y);
    const __nv_bfloat162 h1 = __floats2bfloat162_rn(v.z, v.w);
    const __nv_bfloat162 l0 = __floats2bfloat162_rn(
        v.x - __bfloat162float(__low2bfloat16(h0)), v.y - __bfloat162float(__high2bfloat16(h0)));
    const __nv_bfloat162 l1 = __floats2bfloat162_rn(
        v.z - __bfloat162float(__low2bfloat16(h1)), v.w - __bfloat162float(__high2bfloat16(h1)));
    ((__nv_bfloat162*)g_x_hi)[2 * i]     = h0;
    ((__nv_bfloat162*)g_x_hi)[2 * i + 1] = h1;
    ((__nv_bfloat162*)g_x_lo)[2 * i]     = l0;
    ((__nv_bfloat162*)g_x_lo)[2 * i + 1] = l1;
}
__global__ void split_wm_kernel(const float* __restrict__ src) {
    const int i = blockIdx.x * blockDim.x + threadIdx.x;
    const int n4 = F * D / 4;
    if (i >= n4) return;
    const float4 v = ((const float4*)src)[i];
    const __nv_bfloat162 h0 = __floats2bfloat162_rn(v.x, v.y);
    const __nv_bfloat162 h1 = __floats2bfloat162_rn(v.z, v.w);
    const __nv_bfloat162 l0 = __floats2bfloat162_rn(
        v.x - __bfloat162float(__low2bfloat16(h0)), v.y - __bfloat162float(__high2bfloat16(h0)));
    const __nv_bfloat162 l1 = __floats2bfloat162_rn(
        v.z - __bfloat162float(__low2bfloat16(h1)), v.w - __bfloat162float(__high2bfloat16(h1)));
    ((__nv_bfloat162*)g_wm_hi)[2 * i]     = h0;
    ((__nv_bfloat162*)g_wm_hi)[2 * i + 1] = h1;
    ((__nv_bfloat162*)g_wm_lo)[2 * i]     = l0;
    ((__nv_bfloat162*)g_wm_lo)[2 * i + 1] = l1;
}

// ============================================================================
// K5: gathered+split B for GEMM2: bc[b][e][j] = w_proj[e][sel[b][j]]
// ============================================================================
__global__ void gather_wproj_kernel(const float* __restrict__ wp) {
    const int e = blockIdx.x, b = blockIdx.y;
    const int* sel = g_sel + b * KSEL;
    const float* row = wp + (size_t)e * F;
    __nv_bfloat16* bh = g_bc_hi + (size_t)(b * D + e) * KSEL;
    __nv_bfloat16* bl = g_bc_lo + (size_t)(b * D + e) * KSEL;
    for (int j = threadIdx.x; j < KSEL; j += blockDim.x) {
        const float v = __ldg(row + __ldg(sel + j));
        const __nv_bfloat16 h = __float2bfloat16_rn(v);
        bh[j] = h;
        bl[j] = __float2bfloat16_rn(v - __bfloat162float(h));
    }
}

// ============================================================================
// HMMA GEMM: C[64(m) x 128(n)] per CTA, bf16 hi/lo 3-pass split, m16n8k16.
// 8 warps = 2(m) x 4(n), warp tile 32x32 -> FULL 128-column coverage.
// Static smem: stage = Ahi 2K | Alo 2K | Bhi 4K | Blo 4K = 12KB; 2 stages.
// XOR swizzle unit' = unit ^ ((row>>2)&1) -> conflict-free ldmatrix.
// ALL scratch pointers resolved in DEVICE code via IS_G1 (no host-side
// __device__-symbol args — that was the R3-R7 crash).
//   IS_G1: A = g_x_hi/lo [T,D], B = g_wm_hi/lo gathered via g_sel,
//          K=D, epilogue relu + hi/lo split -> g_h_hi/lo [T,KSEL]
//  !IS_G1: A = g_h_hi/lo [T,KSEL], B = g_bc_hi/lo [D,KSEL] per batch,
//          K=KSEL, fp32 epilogue -> out [T,D]
// ============================================================================
#define A_TILE_B 2048
#define B_TILE_B 4096
#define STAGE_B  12288

template <bool IS_G1>
__global__ void __launch_bounds__(256, 2) gemm_hmma(float* __restrict__ Of) {
    __shared__ __align__(16) char smbuf[2 * STAGE_B];   // 24 KB static
    __shared__ int selc[128];
    const uint32_t sbase = smem_to_u32(smbuf);
    const int tid = threadIdx.x;
    const int b = blockIdx.z;
    const int n0 = blockIdx.x * 128, m0 = blockIdx.y * 64;

    const int lda  = IS_G1 ? D : KSEL;
    const int ldb  = IS_G1 ? D : KSEL;
    const int Kdim = IS_G1 ? D : KSEL;

    const __nv_bfloat16* Ahi = IS_G1 ? (g_x_hi + (size_t)b * T * D)
                                     : (g_h_hi + (size_t)b * T * KSEL);
    const __nv_bfloat16* Alo = IS_G1 ? (g_x_lo + (size_t)b * T * D)
                                     : (g_h_lo + (size_t)b * T * KSEL);
    const __nv_bfloat16* Bhi = IS_G1 ? g_wm_hi : (g_bc_hi + (size_t)b * D * KSEL);
    const __nv_bfloat16* Blo = IS_G1 ? g_wm_lo : (g_bc_lo + (size_t)b * D * KSEL);

    if (IS_G1) {
        if (tid < 128) selc[tid] = g_sel[b * KSEL + n0 + tid];
        __syncthreads();
    }

    // --- cp.async slots ---
    // B: all 256 threads, row r = tid>>1 (0..127), unit u = tid&1
    // A: threads < 128, row r (0..63), unit u
    const int r = tid >> 1, u = tid & 1;
    const uint32_t soff = (uint32_t)(r * 32 + ((u ^ ((r >> 2) & 1)) << 4));
    const int gk = u * 8;
    const bool a_active = tid < 128;
    const int arow = m0 + r;                          // valid when a_active
    const int brow = IS_G1 ? selc[r] : (n0 + r);

    const int nch = Kdim / 16;

    auto load_stage = [&](int stage, int k0) {
        const uint32_t s = sbase + (uint32_t)stage * STAGE_B;
        if (a_active) {
            cp_async16(s + soff, Ahi + (size_t)arow * lda + k0 + gk);
            cp_async16(s + A_TILE_B + soff, Alo + (size_t)arow * lda + k0 + gk);
        }
        cp_async16(s + 2 * A_TILE_B + soff, Bhi + (size_t)brow * ldb + k0 + gk);
        cp_async16(s + 2 * A_TILE_B + B_TILE_B + soff, Blo + (size_t)brow * ldb + k0 + gk);
        cp_commit();
    };

    // --- warp tiling: 8 warps = 2(m) x 4(n), warp tile 32x32 ---
    const int warp = tid >> 5, lane = tid & 31;
    const int wm = warp & 1;          // m base = wm*32
    const int wn = warp >> 1;         // n base = wn*32  (4 x 32 = 128 FULL)
    const int lt = lane >> 3, lri = lane & 7;

    const int a_row_l = (lt & 1) * 8 + lri;   // A matrices m0k0,m8k0,m0k8,m8k8
    const int a_ku    = lt >> 1;
    const int b_row_l = (lt >> 1) * 8 + lri;  // B matrices n0k0,n0k8,n8k0,n8k8
    const int b_ku    = lt & 1;

    uint32_t aoff[2];
    #pragma unroll
    for (int mi = 0; mi < 2; mi++) {
        const int ar = wm * 32 + mi * 16 + a_row_l;
        aoff[mi] = (uint32_t)(ar * 32 + ((a_ku ^ ((ar >> 2) & 1)) << 4));
    }
    uint32_t boff[2];
    #pragma unroll
    for (int g = 0; g < 2; g++) {
        const int br = wn * 32 + g * 16 + b_row_l;
        boff[g] = (uint32_t)(2 * A_TILE_B + br * 32 + ((b_ku ^ ((br >> 2) & 1)) << 4));
    }

    float acc[2][4][4];
    #pragma unroll
    for (int mi = 0; mi < 2; mi++)
        #pragma unroll
        for (int ni = 0; ni < 4; ni++)
            #pragma unroll
            for (int q = 0; q < 4; q++) acc[mi][ni][q] = 0.f;

    load_stage(0, 0);

    for (int ch = 0; ch < nch; ch++) {
        cp_wait0();
        __syncthreads();   // stage-ch data visible; prior iteration's reads done
        if (ch + 1 < nch) load_stage((ch + 1) & 1, (ch + 1) * 16);

        const uint32_t s = sbase + (uint32_t)(ch & 1) * STAGE_B;
        uint32_t ah[2][4], al[2][4], bh[2][4], bl[2][4];
        #pragma unroll
        for (int mi = 0; mi < 2; mi++) {
            ldm_x4(ah[mi], s + aoff[mi]);
            ldm_x4(al[mi], s + A_TILE_B + aoff[mi]);
        }
        #pragma unroll
        for (int g = 0; g < 2; g++) {
            ldm_x4(bh[g], s + boff[g]);
            ldm_x4(bl[g], s + B_TILE_B + boff[g]);
        }

        #pragma unroll
        for (int mi = 0; mi < 2; mi++)
            #pragma unroll
            for (int ni = 0; ni < 4; ni++) {
                const uint32_t* ph = &bh[ni >> 1][(ni & 1) * 2];
                const uint32_t* pl = &bl[ni >> 1][(ni & 1) * 2];
                mma_bf16(acc[mi][ni], ah[mi], ph);  // hi*hi
                mma_bf16(acc[mi][ni], ah[mi], pl);  // hi*lo
                mma_bf16(acc[mi][ni], al[mi], ph);  // lo*hi
            }
    }

    // --- epilogue ---
    const int erow = lane >> 2, ecol = (lane & 3) * 2;
    #pragma unroll
    for (int mi = 0; mi < 2; mi++)
        #pragma unroll
        for (int ni = 0; ni < 4; ni++) {
            const int row = m0 + wm * 32 + mi * 16 + erow;
            const int col = n0 + wn * 32 + ni * 8 + ecol;
            #pragma unroll
            for (int h = 0; h < 2; h++) {   // c0/c1 at row, c2/c3 at row+8
                const int rr = row + h * 8;
                float f0 = acc[mi][ni][h * 2 + 0];
                float f1 = acc[mi][ni][h * 2 + 1];
                if (IS_G1) {
                    f0 = fmaxf(f0, 0.f); f1 = fmaxf(f1, 0.f);
                    const __nv_bfloat162 hp = __floats2bfloat162_rn(f0, f1);
                    const __nv_bfloat162 lp = __floats2bfloat162_rn(
                        f0 - __bfloat162float(__low2bfloat16(hp)),
                        f1 - __bfloat162float(__high2bfloat16(hp)));
                    __nv_bfloat16* hh = g_h_hi + (size_t)b * T * KSEL;
                    __nv_bfloat16* hl = g_h_lo + (size_t)b * T * KSEL;
                    *(uint32_t*)(hh + (size_t)rr * KSEL + col) = bf162_as_u32(hp);
                    *(uint32_t*)(hl + (size_t)rr * KSEL + col) = bf162_as_u32(lp);
                } else {
                    float2 v; v.x = f0; v.y = f1;
                    *(float2*)(Of + ((size_t)b * T + rr) * D + col) = v;
                }
            }
        }
}

// ============================================================================
extern "C" void kernel_launch(void* const* d_in, const int* in_sizes, int n_in,
                              void* d_out, int out_size) {
    const float* x      = (const float*)d_in[0];
    const float* w1     = (const float*)d_in[1];
    const float* w2     = (const float*)d_in[2];
    const float* w_mfc  = (const float*)d_in[3];
    const float* w_proj = (const float*)d_in[4];
    float* out = (float*)d_out;

    pool_partial_kernel<<<BATCH * NPART, 256>>>(x);
    ck_kernel<<<BATCH, 1024>>>(w1, w2);
    topk_kernel<<<BATCH, 1024>>>();
    split_x_kernel<<<(BATCH * T * D / 4 + 255) / 256, 256>>>(x);
    split_wm_kernel<<<(F * D / 4 + 255) / 256, 256>>>(w_mfc);
    gather_wproj_kernel<<<dim3(D, BATCH), 256>>>(w_proj);

    // GEMM1: h = relu(x @ wm_sel^T), gathered-N, relu + hi/lo split epilogue
    gemm_hmma<true><<<dim3(KSEL / 128, T / 64, BATCH), 256>>>(nullptr);

    // GEMM2: out = h @ bc^T, fp32 epilogue (d_out is a real device pointer)
    gemm_hmma<false><<<dim3(D / 128, T / 64, BATCH), 256>>>(out);
}

// round 9
// speedup vs baseline: 2.3067x; 1.0325x over previous
#include <cuda_runtime.h>
#include <cuda_bf16.h>
#include <cstdint>

#define BATCH 8
#define T 1024
#define D 768
#define F 12288
#define CDIM 48
#define KSEL 3072
#define NPART 16
#define TCHUNK (T / NPART)

// -------- device scratch (allocation-free rule: static __device__ globals) ----
// RULE (hard-learned R3-R7): referenced ONLY from device code. Passing these as
// host-side kernel args yields the host shadow address -> crash (rel_err 1.0).
__device__ float g_part[BATCH * NPART * D];
__device__ float g_ck[BATCH * F];
__device__ int   g_sel[BATCH * KSEL];
__device__ __align__(16) __nv_bfloat16 g_x_hi[(size_t)BATCH * T * D];
__device__ __align__(16) __nv_bfloat16 g_x_lo[(size_t)BATCH * T * D];
__device__ __align__(16) __nv_bfloat16 g_wm_hi[(size_t)F * D];
__device__ __align__(16) __nv_bfloat16 g_wm_lo[(size_t)F * D];
__device__ __align__(16) __nv_bfloat16 g_h_hi[(size_t)BATCH * T * KSEL];
__device__ __align__(16) __nv_bfloat16 g_h_lo[(size_t)BATCH * T * KSEL];
__device__ __align__(16) __nv_bfloat16 g_bc_hi[(size_t)BATCH * D * KSEL];
__device__ __align__(16) __nv_bfloat16 g_bc_lo[(size_t)BATCH * D * KSEL];

// ============================================================================
// PTX helpers (base-target only: cp.async / ldmatrix / mma.sync)
// ============================================================================
__device__ __forceinline__ uint32_t smem_to_u32(const void* p) {
    uint32_t a;
    asm("{ .reg .u64 t; cvta.to.shared.u64 t, %1; cvt.u32.u64 %0, t; }" : "=r"(a) : "l"(p));
    return a;
}
__device__ __forceinline__ void cp_async16(uint32_t saddr, const void* gptr) {
    asm volatile("cp.async.cg.shared.global [%0], [%1], 16;" :: "r"(saddr), "l"(gptr) : "memory");
}
__device__ __forceinline__ void cp_commit() { asm volatile("cp.async.commit_group;" ::: "memory"); }
__device__ __forceinline__ void cp_wait0()  { asm volatile("cp.async.wait_group 0;" ::: "memory"); }

__device__ __forceinline__ void ldm_x4(uint32_t* r, uint32_t addr) {
    asm volatile("ldmatrix.sync.aligned.m8n8.x4.shared.b16 {%0,%1,%2,%3}, [%4];"
                 : "=r"(r[0]), "=r"(r[1]), "=r"(r[2]), "=r"(r[3]) : "r"(addr));
}
__device__ __forceinline__ void mma_bf16(float* c, const uint32_t* a, const uint32_t* b) {
    asm volatile("mma.sync.aligned.m16n8k16.row.col.f32.bf16.bf16.f32 "
                 "{%0,%1,%2,%3}, {%4,%5,%6,%7}, {%8,%9}, {%0,%1,%2,%3};"
                 : "+f"(c[0]), "+f"(c[1]), "+f"(c[2]), "+f"(c[3])
                 : "r"(a[0]), "r"(a[1]), "r"(a[2]), "r"(a[3]), "r"(b[0]), "r"(b[1]));
}
__device__ __forceinline__ uint32_t bf162_as_u32(__nv_bfloat162 v) {
    return *reinterpret_cast<uint32_t*>(&v);
}

// ============================================================================
// K1: partial sequence-mean pool (verified)
// ============================================================================
__global__ void pool_partial_kernel(const float* __restrict__ x) {
    const int b = blockIdx.x >> 4;
    const int s = blockIdx.x & 15;
    const float* xp = x + ((size_t)b * T + (size_t)s * TCHUNK) * D;
    for (int d = threadIdx.x; d < D; d += blockDim.x) {
        float acc = 0.f;
        #pragma unroll 4
        for (int t = 0; t < TCHUNK; t++) acc += xp[(size_t)t * D + d];
        g_part[(size_t)blockIdx.x * D + d] = acc;
    }
}

// ============================================================================
// K2: ck = relu(pooled @ w1^T) @ w2^T (verified)
// ============================================================================
__global__ void __launch_bounds__(1024) ck_kernel(const float* __restrict__ w1,
                                                  const float* __restrict__ w2) {
    const int b = blockIdx.x;
    __shared__ float pooled_s[D];
    __shared__ float tmp_s[CDIM];
    const int tid = threadIdx.x;

    for (int d = tid; d < D; d += blockDim.x) {
        float s = 0.f;
        #pragma unroll
        for (int p = 0; p < NPART; p++) s += g_part[(size_t)(b * NPART + p) * D + d];
        pooled_s[d] = s * (1.0f / (float)T);
    }
    __syncthreads();

    const int wid = tid >> 5, lane = tid & 31;
    for (int c = wid; c < CDIM; c += 32) {
        float s = 0.f;
        for (int d = lane; d < D; d += 32) s += pooled_s[d] * w1[(size_t)c * D + d];
        #pragma unroll
        for (int o = 16; o > 0; o >>= 1) s += __shfl_xor_sync(0xFFFFFFFFu, s, o);
        if (lane == 0) tmp_s[c] = fmaxf(s, 0.f);
    }
    __syncthreads();

    for (int f = tid; f < F; f += blockDim.x) {
        const float* w2r = w2 + (size_t)f * CDIM;
        float s = 0.f;
        #pragma unroll
        for (int c = 0; c < CDIM; c++) s += tmp_s[c] * w2r[c];
        g_ck[b * F + f] = s;
    }
}

// ============================================================================
// K3: exact top-KSEL radix select + deterministic compaction (verified)
// ============================================================================
__global__ void __launch_bounds__(1024) topk_kernel() {
    const int b = blockIdx.x;
    const float* ck = g_ck + b * F;

    __shared__ unsigned hist[256];
    __shared__ unsigned s_prefix, s_remaining;
    __shared__ int s_wcnt_gt[32], s_wcnt_eq[32];
    __shared__ int s_woff_gt[32], s_woff_eq[32];
    __shared__ int s_base_gt, s_base_eq;

    const int tid = threadIdx.x;
    unsigned keys[12];
    #pragma unroll
    for (int i = 0; i < 12; i++) {
        unsigned u = __float_as_uint(ck[i * 1024 + tid]);
        keys[i] = (u & 0x80000000u) ? ~u : (u | 0x80000000u);
    }
    if (tid == 0) { s_prefix = 0u; s_remaining = KSEL; }
    unsigned prefix_mask = 0u;
    __syncthreads();

    for (int pass = 0; pass < 4; pass++) {
        const int shift = 24 - 8 * pass;
        if (tid < 256) hist[tid] = 0u;
        __syncthreads();
        const unsigned prefix = s_prefix;
        #pragma unroll
        for (int i = 0; i < 12; i++) {
            if ((keys[i] & prefix_mask) == prefix)
                atomicAdd(&hist[(keys[i] >> shift) & 255u], 1u);
        }
        __syncthreads();
        if (tid == 0) {
            const unsigned rem = s_remaining;
            unsigned cum = 0u;
            int bin = 255;
            for (; bin > 0; bin--) {
                if (cum + hist[bin] >= rem) break;
                cum += hist[bin];
            }
            s_remaining = rem - cum;
            s_prefix = prefix | ((unsigned)bin << shift);
        }
        prefix_mask |= (0xFFu << shift);
        __syncthreads();
    }

    const unsigned thr = s_prefix;
    const int remaining = (int)s_remaining;
    const int gt_total  = KSEL - remaining;

    if (tid == 0) { s_base_gt = 0; s_base_eq = 0; }
    __syncthreads();

    const int wid = tid >> 5, lane = tid & 31;
    const unsigned lmask = (1u << lane) - 1u;
    for (int i = 0; i < 12; i++) {
        const int idx = i * 1024 + tid;
        const unsigned k = keys[i];
        const bool isgt = (k > thr);
        const bool iseq = (k == thr);
        const unsigned bg = __ballot_sync(0xFFFFFFFFu, isgt);
        const unsigned be = __ballot_sync(0xFFFFFFFFu, iseq);
        if (lane == 0) { s_wcnt_gt[wid] = __popc(bg); s_wcnt_eq[wid] = __popc(be); }
        __syncthreads();
        if (tid == 0) {
            int sg = s_base_gt, se = s_base_eq;
            for (int w = 0; w < 32; w++) {
                s_woff_gt[w] = sg; sg += s_wcnt_gt[w];
                s_woff_eq[w] = se; se += s_wcnt_eq[w];
            }
            s_base_gt = sg; s_base_eq = se;
        }
        __syncthreads();
        if (isgt) {
            const int pos = s_woff_gt[wid] + __popc(bg & lmask);
            g_sel[b * KSEL + pos] = idx;
        } else if (iseq) {
            const int er = s_woff_eq[wid] + __popc(be & lmask);
            if (er < remaining) g_sel[b * KSEL + gt_total + er] = idx;
        }
    }
}

// ============================================================================
// K4: fp32 -> bf16 hi/lo splits (x and w_mfc)
// ============================================================================
__global__ void split_x_kernel(const float* __restrict__ src) {
    const int i = blockIdx.x * blockDim.x + threadIdx.x;
    const int n4 = BATCH * T * D / 4;
    if (i >= n4) return;
    const float4 v = ((const float4*)src)[i];
    const __nv_bfloat162 h0 = __floats2bfloat162_rn(v.x, v.y);
    const __nv_bfloat162 h1 = __floats2bfloat162_rn(v.z, v.w);
    const __nv_bfloat162 l0 = __floats2bfloat162_rn(
        v.x - __bfloat162float(__low2bfloat16(h0)), v.y - __bfloat162float(__high2bfloat16(h0)));
    const __nv_bfloat162 l1 = __floats2bfloat162_rn(
        v.z - __bfloat162float(__low2bfloat16(h1)), v.w - __bfloat162float(__high2bfloat16(h1)));
    ((__nv_bfloat162*)g_x_hi)[2 * i]     = h0;
    ((__nv_bfloat162*)g_x_hi)[2 * i + 1] = h1;
    ((__nv_bfloat162*)g_x_lo)[2 * i]     = l0;
    ((__nv_bfloat162*)g_x_lo)[2 * i + 1] = l1;
}
__global__ void split_wm_kernel(const float* __restrict__ src) {
    const int i = blockIdx.x * blockDim.x + threadIdx.x;
    const int n4 = F * D / 4;
    if (i >= n4) return;
    const float4 v = ((const float4*)src)[i];
    const __nv_bfloat162 h0 = __floats2bfloat162_rn(v.x, v.y);
    const __nv_bfloat162 h1 = __floats2bfloat162_rn(v.z, v.w);
    const __nv_bfloat162 l0 = __floats2bfloat162_rn(
        v.x - __bfloat162float(__low2bfloat16(h0)), v.y - __bfloat162float(__high2bfloat16(h0)));
    const __nv_bfloat162 l1 = __floats2bfloat162_rn(
        v.z - __bfloat162float(__low2bfloat16(h1)), v.w - __bfloat162float(__high2bfloat16(h1)));
    ((__nv_bfloat162*)g_wm_hi)[2 * i]     = h0;
    ((__nv_bfloat162*)g_wm_hi)[2 * i + 1] = h1;
    ((__nv_bfloat162*)g_wm_lo)[2 * i]     = l0;
    ((__nv_bfloat162*)g_wm_lo)[2 * i + 1] = l1;
}

// ============================================================================
// K5: gather+split bc[b][e][j] = w_proj[e][sel[b][j]]  — v2:
// one block per e; cache the full 12288-wide row in SMEM as bf16 hi/lo
// (2 x 24KB = 48KB static, the limit), then serve all 8 batches with
// coalesced sel reads + SMEM gathers. L2 traffic ~190MB vs ~600MB random.
// ============================================================================
__global__ void __launch_bounds__(256) gather_wproj_kernel(const float* __restrict__ wp) {
    __shared__ __nv_bfloat16 rh[F];   // 24576 B
    __shared__ __nv_bfloat16 rl[F];   // 24576 B  (total 49152 = 48KB static)
    const int e = blockIdx.x;
    const int tid = threadIdx.x;
    const float* row = wp + (size_t)e * F;

    for (int f = tid; f < F; f += 256) {
        const float v = row[f];
        const __nv_bfloat16 h = __float2bfloat16_rn(v);
        rh[f] = h;
        rl[f] = __float2bfloat16_rn(v - __bfloat162float(h));
    }
    __syncthreads();

    for (int b = 0; b < BATCH; b++) {
        const int* sel = g_sel + b * KSEL;
        __nv_bfloat16* bh = g_bc_hi + (size_t)(b * D + e) * KSEL;
        __nv_bfloat16* bl = g_bc_lo + (size_t)(b * D + e) * KSEL;
        for (int j = tid; j < KSEL; j += 256) {
            const int f = __ldg(sel + j);   // coalesced
            bh[j] = rh[f];
            bl[j] = rl[f];
        }
    }
}

// ============================================================================
// HMMA GEMM: C[128(m) x 128(n)] per CTA, bf16 hi/lo 3-pass split, m16n8k16.
// 8 warps = 2(m) x 4(n), warp tile 64x32 -> full 128x128 coverage.
// BM=128 doubles per-chunk compute (~384cyc > L2 latency) so the 2-stage
// cp.async pipeline actually hides the load, and halves L2 tile traffic.
// Static smem: stage = Ahi 4K | Alo 4K | Bhi 4K | Blo 4K = 16KB; 2 stages
// = 32KB (+selc) -> no opt-in, 2 CTAs/SM.
// XOR swizzle unit' = unit ^ ((row>>2)&1) -> conflict-free ldmatrix.
//   IS_G1: A = g_x_hi/lo [T,D], B = g_wm_hi/lo gathered via g_sel, K=D,
//          epilogue relu + hi/lo split -> g_h_hi/lo [T,KSEL]
//  !IS_G1: A = g_h_hi/lo [T,KSEL], B = g_bc_hi/lo [D,KSEL] per batch,
//          K=KSEL, fp32 epilogue -> out [T,D]
// ============================================================================
#define A_TILE_B 4096
#define B_TILE_B 4096
#define STAGE_B  16384

template <bool IS_G1>
__global__ void __launch_bounds__(256, 2) gemm_hmma(float* __restrict__ Of) {
    __shared__ __align__(16) char smbuf[2 * STAGE_B];   // 32 KB static
    __shared__ int selc[128];
    const uint32_t sbase = smem_to_u32(smbuf);
    const int tid = threadIdx.x;
    const int b = blockIdx.z;
    const int n0 = blockIdx.x * 128, m0 = blockIdx.y * 128;

    const int lda  = IS_G1 ? D : KSEL;
    const int ldb  = IS_G1 ? D : KSEL;
    const int Kdim = IS_G1 ? D : KSEL;

    const __nv_bfloat16* Ahi = IS_G1 ? (g_x_hi + (size_t)b * T * D)
                                     : (g_h_hi + (size_t)b * T * KSEL);
    const __nv_bfloat16* Alo = IS_G1 ? (g_x_lo + (size_t)b * T * D)
                                     : (g_h_lo + (size_t)b * T * KSEL);
    const __nv_bfloat16* Bhi = IS_G1 ? g_wm_hi : (g_bc_hi + (size_t)b * D * KSEL);
    const __nv_bfloat16* Blo = IS_G1 ? g_wm_lo : (g_bc_lo + (size_t)b * D * KSEL);

    if (IS_G1) {
        if (tid < 128) selc[tid] = g_sel[b * KSEL + n0 + tid];
        __syncthreads();
    }

    // --- cp.async slots: row r = tid>>1 (0..127), 16B unit u = tid&1 ---
    const int r = tid >> 1, u = tid & 1;
    const uint32_t soff = (uint32_t)(r * 32 + ((u ^ ((r >> 2) & 1)) << 4));
    const int gk = u * 8;
    const int arow = m0 + r;
    const int brow = IS_G1 ? selc[r] : (n0 + r);

    const int nch = Kdim / 16;

    auto load_stage = [&](int stage, int k0) {
        const uint32_t s = sbase + (uint32_t)stage * STAGE_B;
        cp_async16(s + soff, Ahi + (size_t)arow * lda + k0 + gk);
        cp_async16(s + A_TILE_B + soff, Alo + (size_t)arow * lda + k0 + gk);
        cp_async16(s + 2 * A_TILE_B + soff, Bhi + (size_t)brow * ldb + k0 + gk);
        cp_async16(s + 2 * A_TILE_B + B_TILE_B + soff, Blo + (size_t)brow * ldb + k0 + gk);
        cp_commit();
    };

    // --- warp tiling: 8 warps = 2(m) x 4(n), warp tile 64x32 ---
    const int warp = tid >> 5, lane = tid & 31;
    const int wm = warp & 1;          // m base = wm*64
    const int wn = warp >> 1;         // n base = wn*32
    const int lt = lane >> 3, lri = lane & 7;

    const int a_row_l = (lt & 1) * 8 + lri;   // A matrices m0k0,m8k0,m0k8,m8k8
    const int a_ku    = lt >> 1;
    const int b_row_l = (lt >> 1) * 8 + lri;  // B matrices n0k0,n0k8,n8k0,n8k8
    const int b_ku    = lt & 1;

    uint32_t aoff[4];
    #pragma unroll
    for (int mi = 0; mi < 4; mi++) {
        const int ar = wm * 64 + mi * 16 + a_row_l;
        aoff[mi] = (uint32_t)(ar * 32 + ((a_ku ^ ((ar >> 2) & 1)) << 4));
    }
    uint32_t boff[2];
    #pragma unroll
    for (int g = 0; g < 2; g++) {
        const int br = wn * 32 + g * 16 + b_row_l;
        boff[g] = (uint32_t)(2 * A_TILE_B + br * 32 + ((b_ku ^ ((br >> 2) & 1)) << 4));
    }

    float acc[4][4][4];
    #pragma unroll
    for (int mi = 0; mi < 4; mi++)
        #pragma unroll
        for (int ni = 0; ni < 4; ni++)
            #pragma unroll
            for (int q = 0; q < 4; q++) acc[mi][ni][q] = 0.f;

    load_stage(0, 0);

    for (int ch = 0; ch < nch; ch++) {
        cp_wait0();
        __syncthreads();   // stage-ch data visible; prior iteration's reads done
        if (ch + 1 < nch) load_stage((ch + 1) & 1, (ch + 1) * 16);

        const uint32_t s = sbase + (uint32_t)(ch & 1) * STAGE_B;
        uint32_t ah[4][4], al[4][4], bh[2][4], bl[2][4];
        #pragma unroll
        for (int mi = 0; mi < 4; mi++) {
            ldm_x4(ah[mi], s + aoff[mi]);
            ldm_x4(al[mi], s + A_TILE_B + aoff[mi]);
        }
        #pragma unroll
        for (int g = 0; g < 2; g++) {
            ldm_x4(bh[g], s + boff[g]);
            ldm_x4(bl[g], s + B_TILE_B + boff[g]);
        }

        #pragma unroll
        for (int mi = 0; mi < 4; mi++)
            #pragma unroll
            for (int ni = 0; ni < 4; ni++) {
                const uint32_t* ph = &bh[ni >> 1][(ni & 1) * 2];
                const uint32_t* pl = &bl[ni >> 1][(ni & 1) * 2];
                mma_bf16(acc[mi][ni], ah[mi], ph);  // hi*hi
                mma_bf16(acc[mi][ni], ah[mi], pl);  // hi*lo
                mma_bf16(acc[mi][ni], al[mi], ph);  // lo*hi
            }
    }

    // --- epilogue ---
    const int erow = lane >> 2, ecol = (lane & 3) * 2;
    #pragma unroll
    for (int mi = 0; mi < 4; mi++)
        #pragma unroll
        for (int ni = 0; ni < 4; ni++) {
            const int row = m0 + wm * 64 + mi * 16 + erow;
            const int col = n0 + wn * 32 + ni * 8 + ecol;
            #pragma unroll
            for (int h = 0; h < 2; h++) {   // c0/c1 at row, c2/c3 at row+8
                const int rr = row + h * 8;
                float f0 = acc[mi][ni][h * 2 + 0];
                float f1 = acc[mi][ni][h * 2 + 1];
                if (IS_G1) {
                    f0 = fmaxf(f0, 0.f); f1 = fmaxf(f1, 0.f);
                    const __nv_bfloat162 hp = __floats2bfloat162_rn(f0, f1);
                    const __nv_bfloat162 lp = __floats2bfloat162_rn(
                        f0 - __bfloat162float(__low2bfloat16(hp)),
                        f1 - __bfloat162float(__high2bfloat16(hp)));
                    __nv_bfloat16* hh = g_h_hi + (size_t)b * T * KSEL;
                    __nv_bfloat16* hl = g_h_lo + (size_t)b * T * KSEL;
                    *(uint32_t*)(hh + (size_t)rr * KSEL + col) = bf162_as_u32(hp);
                    *(uint32_t*)(hl + (size_t)rr * KSEL + col) = bf162_as_u32(lp);
                } else {
                    float2 v; v.x = f0; v.y = f1;
                    *(float2*)(Of + ((size_t)b * T + rr) * D + col) = v;
                }
            }
        }
}

// ============================================================================
extern "C" void kernel_launch(void* const* d_in, const int* in_sizes, int n_in,
                              void* d_out, int out_size) {
    const float* x      = (const float*)d_in[0];
    const float* w1     = (const float*)d_in[1];
    const float* w2     = (const float*)d_in[2];
    const float* w_mfc  = (const float*)d_in[3];
    const float* w_proj = (const float*)d_in[4];
    float* out = (float*)d_out;

    pool_partial_kernel<<<BATCH * NPART, 256>>>(x);
    ck_kernel<<<BATCH, 1024>>>(w1, w2);
    topk_kernel<<<BATCH, 1024>>>();
    split_x_kernel<<<(BATCH * T * D / 4 + 255) / 256, 256>>>(x);
    split_wm_kernel<<<(F * D / 4 + 255) / 256, 256>>>(w_mfc);
    gather_wproj_kernel<<<D, 256>>>(w_proj);

    // GEMM1: h = relu(x @ wm_sel^T), gathered-N, relu + hi/lo split epilogue
    gemm_hmma<true><<<dim3(KSEL / 128, T / 128, BATCH), 256>>>(nullptr);

    // GEMM2: out = h @ bc^T, fp32 epilogue (d_out is a real device pointer)
    gemm_hmma<false><<<dim3(D / 128, T / 128, BATCH), 256>>>(out);
}